// round 1
// baseline (speedup 1.0000x reference)
#include <cuda_runtime.h>
#include <math.h>

#define B 8
#define T 2048
#define C 1024
#define H 128
#define BT (B * T)

// Scratch for projected Q/K/V: 3 x 8MB (device globals, no allocation)
__device__ float g_Q[BT * H];
__device__ float g_K[BT * H];
__device__ float g_V[BT * H];

// ---------------------------------------------------------------------------
// Projection: out[m][n] = sum_k x[m][k] * W[k][n],  M=BT, K=C, N=H
// Grid: (BT/64, 3)  blockIdx.y selects Wq/Wk/Wv -> g_Q/g_K/g_V
// Block: 256 threads, 64x128 output tile, K-chunks of 32, 4x8 micro-tile.
// ---------------------------------------------------------------------------
__global__ __launch_bounds__(256) void proj_kernel(
    const float* __restrict__ x,
    const float* __restrict__ Wq,
    const float* __restrict__ Wk,
    const float* __restrict__ Wv)
{
    __shared__ float xs[64][33];    // padded: conflict-free row reads
    __shared__ float ws[32][128];

    const float* W  = (blockIdx.y == 0) ? Wq : (blockIdx.y == 1) ? Wk : Wv;
    float*       out = (blockIdx.y == 0) ? g_Q : (blockIdx.y == 1) ? g_K : g_V;

    const int m0  = blockIdx.x * 64;
    const int tid = threadIdx.x;
    const int ty  = tid >> 4;      // 0..15 -> q-row group
    const int tx  = tid & 15;      // 0..15 -> col group

    float acc[4][8];
    #pragma unroll
    for (int i = 0; i < 4; i++)
        #pragma unroll
        for (int j = 0; j < 8; j++) acc[i][j] = 0.0f;

    for (int k0 = 0; k0 < C; k0 += 32) {
        // load x tile 64x32
        #pragma unroll
        for (int i = tid; i < 64 * 32; i += 256) {
            int r = i >> 5, c = i & 31;
            xs[r][c] = x[(size_t)(m0 + r) * C + k0 + c];
        }
        // load W tile 32x128
        #pragma unroll
        for (int i = tid; i < 32 * 128; i += 256) {
            int r = i >> 7, c = i & 127;
            ws[r][c] = W[(size_t)(k0 + r) * H + c];
        }
        __syncthreads();

        #pragma unroll
        for (int kk = 0; kk < 32; kk++) {
            float a[4], bb[8];
            #pragma unroll
            for (int i = 0; i < 4; i++) a[i] = xs[i * 16 + ty][kk];
            #pragma unroll
            for (int j = 0; j < 8; j++) bb[j] = ws[kk][j * 16 + tx];
            #pragma unroll
            for (int i = 0; i < 4; i++)
                #pragma unroll
                for (int j = 0; j < 8; j++) acc[i][j] = fmaf(a[i], bb[j], acc[i][j]);
        }
        __syncthreads();
    }

    #pragma unroll
    for (int i = 0; i < 4; i++) {
        int m = m0 + i * 16 + ty;
        #pragma unroll
        for (int j = 0; j < 8; j++) {
            out[(size_t)m * H + j * 16 + tx] = acc[i][j];
        }
    }
}

// ---------------------------------------------------------------------------
// Flash attention (fp32, causal): one CTA per (batch, 64-query tile).
// 256 threads. S = Q K^T (4x4 micro-tile), online softmax (shfl over 16-lane
// row groups), P staged in smem, O += P V (4x8 micro-tile).
// ---------------------------------------------------------------------------
#define QSTRIDE 129
#define KSTRIDE 129
#define VSTRIDE 128
#define PSTRIDE 65

__global__ __launch_bounds__(256) void attn_kernel(float* __restrict__ out)
{
    extern __shared__ float sm[];
    float* Qs = sm;                       // 64 * 129
    float* Ks = Qs + 64 * QSTRIDE;        // 64 * 129
    float* Vs = Ks + 64 * KSTRIDE;        // 64 * 128
    float* Ps = Vs + 64 * VSTRIDE;        // 64 * 65

    const int b   = blockIdx.y;
    const int q0  = blockIdx.x * 64;
    const int tid = threadIdx.x;
    const int ty  = tid >> 4;
    const int tx  = tid & 15;

    const float* Qg = g_Q + (size_t)b * T * H;
    const float* Kg = g_K + (size_t)b * T * H;
    const float* Vg = g_V + (size_t)b * T * H;

    // Load Q tile once
    #pragma unroll
    for (int i = tid; i < 64 * H; i += 256) {
        int r = i >> 7, c = i & 127;
        Qs[r * QSTRIDE + c] = Qg[(size_t)(q0 + r) * H + c];
    }

    float m_i[4], l_i[4], o[4][8];
    #pragma unroll
    for (int i = 0; i < 4; i++) {
        m_i[i] = -INFINITY;
        l_i[i] = 0.0f;
        #pragma unroll
        for (int j = 0; j < 8; j++) o[i][j] = 0.0f;
    }

    const float scale = 0.08838834764831845f;  // 1/sqrt(128)
    const int ntiles = q0 / 64 + 1;            // causal: skip tiles above diag

    for (int t = 0; t < ntiles; t++) {
        const int s0 = t * 64;
        __syncthreads();   // previous iteration's consumers done before overwrite
        #pragma unroll
        for (int i = tid; i < 64 * H; i += 256) {
            int r = i >> 7, c = i & 127;
            Ks[r * KSTRIDE + c] = Kg[(size_t)(s0 + r) * H + c];
            Vs[r * VSTRIDE + c] = Vg[(size_t)(s0 + r) * H + c];
        }
        __syncthreads();

        // S = Q K^T  (4x4 per thread)
        float s_acc[4][4];
        #pragma unroll
        for (int i = 0; i < 4; i++)
            #pragma unroll
            for (int j = 0; j < 4; j++) s_acc[i][j] = 0.0f;

        #pragma unroll 4
        for (int h = 0; h < H; h++) {
            float a[4], bb[4];
            #pragma unroll
            for (int i = 0; i < 4; i++) a[i] = Qs[(i * 16 + ty) * QSTRIDE + h];
            #pragma unroll
            for (int j = 0; j < 4; j++) bb[j] = Ks[(j * 16 + tx) * KSTRIDE + h];
            #pragma unroll
            for (int i = 0; i < 4; i++)
                #pragma unroll
                for (int j = 0; j < 4; j++)
                    s_acc[i][j] = fmaf(a[i], bb[j], s_acc[i][j]);
        }

        const bool diag = (s0 == q0);

        // scale + causal mask + online softmax
        #pragma unroll
        for (int i = 0; i < 4; i++) {
            const int qi = i * 16 + ty;
            float z[4];
            #pragma unroll
            for (int j = 0; j < 4; j++) {
                float v = s_acc[i][j] * scale;
                if (diag && (j * 16 + tx) > qi) v = -INFINITY;
                z[j] = v;
            }
            float mt = fmaxf(fmaxf(z[0], z[1]), fmaxf(z[2], z[3]));
            #pragma unroll
            for (int off = 8; off >= 1; off >>= 1)
                mt = fmaxf(mt, __shfl_xor_sync(0xffffffffu, mt, off, 16));

            const float mnew  = fmaxf(m_i[i], mt);
            const float alpha = __expf(m_i[i] - mnew);

            float rowsum = 0.0f;
            float p[4];
            #pragma unroll
            for (int j = 0; j < 4; j++) {
                p[j] = __expf(z[j] - mnew);
                rowsum += p[j];
            }
            #pragma unroll
            for (int off = 8; off >= 1; off >>= 1)
                rowsum += __shfl_xor_sync(0xffffffffu, rowsum, off, 16);

            l_i[i] = l_i[i] * alpha + rowsum;
            m_i[i] = mnew;
            #pragma unroll
            for (int j = 0; j < 8; j++) o[i][j] *= alpha;
            #pragma unroll
            for (int j = 0; j < 4; j++)
                Ps[qi * PSTRIDE + j * 16 + tx] = p[j];
        }
        __syncthreads();

        // O += P @ V  (4x8 per thread)
        #pragma unroll 4
        for (int kk = 0; kk < 64; kk++) {
            float pv[4], vv[8];
            #pragma unroll
            for (int i = 0; i < 4; i++) pv[i] = Ps[(i * 16 + ty) * PSTRIDE + kk];
            #pragma unroll
            for (int j = 0; j < 8; j++) vv[j] = Vs[kk * VSTRIDE + j * 16 + tx];
            #pragma unroll
            for (int i = 0; i < 4; i++)
                #pragma unroll
                for (int j = 0; j < 8; j++)
                    o[i][j] = fmaf(pv[i], vv[j], o[i][j]);
        }
    }

    // Normalize and write
    float* Og = out + (size_t)b * T * H;
    #pragma unroll
    for (int i = 0; i < 4; i++) {
        const float inv_l = 1.0f / l_i[i];
        const int m = q0 + i * 16 + ty;
        #pragma unroll
        for (int j = 0; j < 8; j++)
            Og[(size_t)m * H + j * 16 + tx] = o[i][j] * inv_l;
    }
}

extern "C" void kernel_launch(void* const* d_in, const int* in_sizes, int n_in,
                              void* d_out, int out_size)
{
    const float* x  = (const float*)d_in[0];
    const float* Wq = (const float*)d_in[1];
    const float* Wk = (const float*)d_in[2];
    const float* Wv = (const float*)d_in[3];
    float* out = (float*)d_out;

    // 1) QKV projections
    proj_kernel<<<dim3(BT / 64, 3), 256>>>(x, Wq, Wk, Wv);

    // 2) Flash attention
    const int smem_bytes = (64 * (QSTRIDE + KSTRIDE + VSTRIDE + PSTRIDE)) * sizeof(float);
    cudaFuncSetAttribute(attn_kernel, cudaFuncAttributeMaxDynamicSharedMemorySize, smem_bytes);
    attn_kernel<<<dim3(T / 64, B), 256, smem_bytes>>>(out);
}